// round 9
// baseline (speedup 1.0000x reference)
#include <cuda_runtime.h>
#include <cuda_bf16.h>
#include <math.h>

// Problem constants
#define BB 4
#define CC 32
#define WW 256
#define HH 256
#define KK 9
#define OC_OFF 10
#define PIX (WW*HH)

// k_main (mma) tile: 4 w-rows x 32 h-cols = 128 px, 256 threads (8 warps x 16 px)
#define RR 14              // x rows: w0-5 .. w0+8
#define PCW 43             // pair columns: h0-5 .. h0+37
#define PLANE (RR*PCW)     // 602 float2 per channel
#define NCI2 8
#define XDSZ (NCI2*PLANE)  // 4816 float2

typedef unsigned long long u64;
typedef unsigned int u32;

__device__ __forceinline__ u64 ffma2(u64 a, u64 b, u64 c) {
    u64 d;
    asm("fma.rn.f32x2 %0, %1, %2, %3;" : "=l"(d) : "l"(a), "l"(b), "l"(c));
    return d;
}
__device__ __forceinline__ u64 pack2(float v) {
    u64 d; unsigned u = __float_as_uint(v);
    asm("mov.b64 %0, {%1, %1};" : "=l"(d) : "r"(u));
    return d;
}
__device__ __forceinline__ void unpack2(u64 in, float& lo, float& hi) {
    unsigned a, b;
    asm("mov.b64 {%0, %1}, %2;" : "=r"(a), "=r"(b) : "l"(in));
    lo = __uint_as_float(a); hi = __uint_as_float(b);
}
__device__ __forceinline__ u32 tf32r(float v) {
    u32 r;
    asm("cvt.rna.tf32.f32 %0, %1;" : "=r"(r) : "f"(v));
    return r;
}
__device__ __forceinline__ void mma_tf32(float c[4], u32 a0, u32 a1, u32 a2, u32 a3,
                                         u32 b0, u32 b1) {
    asm("mma.sync.aligned.m16n8k8.row.col.f32.tf32.tf32.f32 "
        "{%0,%1,%2,%3}, {%4,%5,%6,%7}, {%8,%9}, {%0,%1,%2,%3};"
        : "+f"(c[0]), "+f"(c[1]), "+f"(c[2]), "+f"(c[3])
        : "r"(a0), "r"(a1), "r"(a2), "r"(a3), "r"(b0), "r"(b1));
}

// Scratch (zero-initialized at module load; stats arrays are re-zeroed by
// their consumer kernels each run, so every kernel_launch call sees zeros)
__device__ float g_off[BB*OC_OFF*PIX];
__device__ float g_py [BB*KK*PIX];
__device__ float g_pre[BB*CC*PIX];
__device__ float g_soff[BB*5*2];
__device__ float g_mroff[BB*5*2];
__device__ float g_sout[BB*8*2];
__device__ float g_mrout[BB*8*2];

// ---------------------- K1: 3x3 conv, 32 -> 10 ch, 4 pixels (w-rows) / thread
__global__ void __launch_bounds__(256, 2)
k_conv_off(const float* __restrict__ x,
           const float* __restrict__ w_off,
           const float* __restrict__ b_off) {
    __shared__ __align__(8) float ws[CC*9*OC_OFF];   // [ci][tap][10]
    __shared__ float s_sum[5], s_sq[5];
    int b   = blockIdx.y;
    int wb  = blockIdx.x * 4;
    int tid = threadIdx.x;
    int h   = tid;

    for (int i = tid; i < CC*9*OC_OFF; i += 256) {
        int o = i % OC_OFF; int rest = i / OC_OFF;
        int tap = rest % 9; int ci = rest / 9;
        int dy = tap / 3, dx = tap % 3;
        ws[i] = w_off[((o*CC + ci)*3 + dy)*3 + dx];
    }
    if (tid < 5) { s_sum[tid] = 0.f; s_sq[tid] = 0.f; }
    __syncthreads();

    u64 acc[4][5];
    const u64* b2 = (const u64*)b_off;
#pragma unroll
    for (int p = 0; p < 4; p++)
#pragma unroll
        for (int j = 0; j < 5; j++) acc[p][j] = b2[j];

    const float* xb = x + b*CC*PIX;
#pragma unroll 1
    for (int ci = 0; ci < CC; ci++) {
        const float* xc = xb + ci*PIX;
        u64 v2[6][3];
#pragma unroll
        for (int rr = 0; rr < 6; rr++) {
            int r = wb - 1 + rr;
            bool rok = (unsigned)r < 256u;
#pragma unroll
            for (int dx = 0; dx < 3; dx++) {
                int c = h + dx - 1;
                float v = (rok && (unsigned)c < 256u) ? xc[r*256 + c] : 0.f;
                v2[rr][dx] = pack2(v);
            }
        }
#pragma unroll
        for (int tap = 0; tap < 9; tap++) {
            int dy = tap / 3, dx = tap % 3;
            const u64* wp = (const u64*)&ws[(ci*9 + tap)*OC_OFF];
            u64 w0 = wp[0], w1 = wp[1], w2 = wp[2], w3 = wp[3], w4 = wp[4];
#pragma unroll
            for (int p = 0; p < 4; p++) {
                u64 vv = v2[dy + p][dx];
                acc[p][0] = ffma2(vv, w0, acc[p][0]);
                acc[p][1] = ffma2(vv, w1, acc[p][1]);
                acc[p][2] = ffma2(vv, w2, acc[p][2]);
                acc[p][3] = ffma2(vv, w3, acc[p][3]);
                acc[p][4] = ffma2(vv, w4, acc[p][4]);
            }
        }
    }

    float s[5], q[5];
#pragma unroll
    for (int j = 0; j < 5; j++) { s[j] = 0.f; q[j] = 0.f; }
#pragma unroll
    for (int p = 0; p < 4; p++) {
        int w = wb + p;
        float* outp = g_off + b*OC_OFF*PIX + w*256 + h;
#pragma unroll
        for (int j = 0; j < 5; j++) {
            float v0, v1; unpack2(acc[p][j], v0, v1);
            outp[(2*j)*PIX]   = v0;
            outp[(2*j+1)*PIX] = v1;
            s[j] += v0 + v1;
            q[j] += v0*v0 + v1*v1;
        }
    }
#pragma unroll
    for (int j = 0; j < 5; j++) {
        float ss = s[j], qq = q[j];
#pragma unroll
        for (int off = 16; off; off >>= 1) {
            ss += __shfl_xor_sync(0xffffffffu, ss, off);
            qq += __shfl_xor_sync(0xffffffffu, qq, off);
        }
        if ((tid & 31) == 0) { atomicAdd(&s_sum[j], ss); atomicAdd(&s_sq[j], qq); }
    }
    __syncthreads();
    if (tid < 5) {
        atomicAdd(&g_soff[(b*5 + tid)*2 + 0], s_sum[tid]);
        atomicAdd(&g_soff[(b*5 + tid)*2 + 1], s_sq[tid]);
    }
}

// ------------- K2a: finalize offset GN stats (and re-zero accumulators)
__global__ void k_stats_off() {
    int t = threadIdx.x;
    if (t < BB*5) {
        float S = g_soff[t*2], Q = g_soff[t*2 + 1];
        float inv = 1.f / (2.f * (float)PIX);
        float mu  = S * inv;
        float var = Q * inv - mu*mu;
        g_mroff[t*2]     = mu;
        g_mroff[t*2 + 1] = rsqrtf(var + 1e-5f);
        g_soff[t*2]     = 0.f;
        g_soff[t*2 + 1] = 0.f;
    }
}

// --------------------- K3: GN + tanh + cumsum -> sampling coordinate field py
__global__ void k_py(const float* __restrict__ sc, const float* __restrict__ bi) {
    int b = blockIdx.y;
    int p = blockIdx.x*256 + threadIdx.x;
    int w = p >> 8;

    float t[9];
#pragma unroll
    for (int c = 0; c < 9; c++) {
        float v  = g_off[(b*OC_OFF + c)*PIX + p];
        int   g  = c >> 1;
        float mu = g_mroff[(b*5 + g)*2], rs = g_mroff[(b*5 + g)*2 + 1];
        t[c] = tanhf(fmaf((v - mu)*rs, sc[c], bi[c]));
    }
    float yc[9];
    float r0 = t[3];
    float r1 = r0 + t[2];
    float r2 = r1 + t[1];
    float r3 = r2 + t[0];
    yc[0] = r3; yc[1] = r2; yc[2] = r1; yc[3] = r0;
    yc[4] = 0.f;
    float u0 = t[5];
    float u1 = u0 + t[6];
    float u2 = u1 + t[7];
    float u3 = u2 + t[8];
    yc[5] = u0; yc[6] = u1; yc[7] = u2; yc[8] = u3;

#pragma unroll
    for (int k = 0; k < 9; k++) {
        float y  = (float)w + yc[k];
        float tt = fminf(fmaxf(y * (1.f/256.f), 0.f), 1.f);
        g_py[(b*KK + k)*PIX + p] = tt * 255.f;
    }
}

// -------- K4: fused bilinear-sample + (K,1)-strided conv via tf32 mma.sync
#define SM_GEOW 0
#define SM_XSD  18432
#define SM_BP   56960
#define SM_GEOO 93824
#define SM_STAT 103040
#define SMEM_MAIN (103104 + 64)

__global__ void __launch_bounds__(256, 2)
k_main(const float* __restrict__ x,
       const float* __restrict__ wdsc,
       const float* __restrict__ bdsc) {
    extern __shared__ __align__(16) char smraw[];
    float4* geoW = (float4*)(smraw + SM_GEOW);
    float2* XsD  = (float2*)(smraw + SM_XSD);
    uint2*  Bp   = (uint2*) (smraw + SM_BP);
    int2*   geoO = (int2*)  (smraw + SM_GEOO);
    float*  sOs  = (float*) (smraw + SM_STAT);
    float*  sOq  = sOs + 8;

    int b  = blockIdx.z;
    int w0 = blockIdx.y * 4;
    int h0 = blockIdx.x * 32;
    int tid = threadIdx.x;
    int warp = tid >> 5;
    int T = tid & 31;
    int rbase = w0 - 5, cbase = h0 - 5;

    // --- pack B fragments (tf32-rounded, per-lane layout) ---
    for (int i = tid; i < 4*9*4*32; i += 256) {
        int lane = i & 31; int rest = i >> 5;
        int nb = rest & 3; rest >>= 2;
        int kk = rest % 9; int q = rest / 9;
        int c8 = lane & 3, co = nb*8 + (lane >> 2);
        float wv0 = wdsc[(co*CC + q*8 + c8)*KK + kk];
        float wv1 = wdsc[(co*CC + q*8 + c8 + 4)*KK + kk];
        Bp[i] = make_uint2(tf32r(wv0), tf32r(wv1));
    }
    // --- geometry table: per (local px, kk) ---
    for (int i = tid; i < 128*9; i += 256) {
        int kk = i % 9; int p = i / 9;
        int w = w0 + (p >> 5), h = h0 + (p & 31);
        float py = g_py[(b*KK + kk)*PIX + w*256 + h];
        float y0f = floorf(py);
        float wy  = py - y0f;
        int y0 = (int)y0f;
        int y1 = min(y0 + 1, 255);
        int rs0 = y0 - rbase, rs1 = y1 - rbase;
        float fx = (float)(h + kk - 4);
        float pxv = fminf(fmaxf(fx * (1.f/256.f), 0.f), 1.f) * 255.f;
        float x0f = floorf(pxv);
        float wx  = pxv - x0f;
        int cs0 = (int)x0f - cbase;
        geoW[i] = make_float4((1.f-wy)*(1.f-wx), (1.f-wy)*wx, wy*(1.f-wx), wy*wx);
        geoO[i] = make_int2(rs0*PCW + cs0, rs1*PCW + cs0);
    }
    if (tid < 8) { sOs[tid] = 0.f; sOq[tid] = 0.f; }

    float c[4][4];
#pragma unroll
    for (int nb = 0; nb < 4; nb++)
#pragma unroll
        for (int j = 0; j < 4; j++) c[nb][j] = 0.f;

    int p0 = (warp << 4) + (T >> 2);
    int p1 = p0 + 8;
    const float2* Pl0 = XsD + (T & 3)*PLANE;
    const float2* Pl1 = XsD + ((T & 3) + 4)*PLANE;

#pragma unroll 1
    for (int q = 0; q < 4; q++) {
        __syncthreads();
        // stage 8-channel pair tile: warp-per-row, pairs via shuffle
        {
            const float* xq = x + (b*CC + q*NCI2)*PIX;
            int gc_a = min(max(cbase + T, 0), 255);
            int gc_b = min(max(cbase + T + 32, 0), 255);
#pragma unroll 1
            for (int idx = warp; idx < NCI2*RR; idx += 8) {
                int ci8 = idx / RR, r = idx % RR;
                int gr = min(max(rbase + r, 0), 255);
                const float* rowp = xq + ci8*PIX + gr*256;
                float va = __ldg(&rowp[gc_a]);
                float vb = __ldg(&rowp[gc_b]);
                float va1 = __shfl_down_sync(0xffffffffu, va, 1);
                float vb1 = __shfl_down_sync(0xffffffffu, vb, 1);
                float vb0 = __shfl_sync(0xffffffffu, vb, 0);
                if (T == 31) va1 = vb0;
                float2* dst = XsD + ci8*PLANE + r*PCW;
                dst[T] = make_float2(va, va1);
                if (T < PCW - 32) dst[T + 32] = make_float2(vb, vb1);
            }
        }
        __syncthreads();

#pragma unroll 1
        for (int kk = 0; kk < 9; kk++) {
            float4 gw0 = geoW[p0*9 + kk]; int2 go0 = geoO[p0*9 + kk];
            float4 gw1 = geoW[p1*9 + kk]; int2 go1 = geoO[p1*9 + kk];

            float2 A00 = Pl0[go0.x], A01 = Pl0[go0.y];
            float v0 = gw0.x*A00.x;
            v0 = fmaf(gw0.y, A00.y, v0);
            v0 = fmaf(gw0.z, A01.x, v0);
            v0 = fmaf(gw0.w, A01.y, v0);
            float2 A10 = Pl0[go1.x], A11 = Pl0[go1.y];
            float v1 = gw1.x*A10.x;
            v1 = fmaf(gw1.y, A10.y, v1);
            v1 = fmaf(gw1.z, A11.x, v1);
            v1 = fmaf(gw1.w, A11.y, v1);
            float2 A20 = Pl1[go0.x], A21 = Pl1[go0.y];
            float v2 = gw0.x*A20.x;
            v2 = fmaf(gw0.y, A20.y, v2);
            v2 = fmaf(gw0.z, A21.x, v2);
            v2 = fmaf(gw0.w, A21.y, v2);
            float2 A30 = Pl1[go1.x], A31 = Pl1[go1.y];
            float v3 = gw1.x*A30.x;
            v3 = fmaf(gw1.y, A30.y, v3);
            v3 = fmaf(gw1.z, A31.x, v3);
            v3 = fmaf(gw1.w, A31.y, v3);

            u32 a0 = tf32r(v0), a1 = tf32r(v1), a2 = tf32r(v2), a3 = tf32r(v3);

            const uint2* bp = Bp + ((q*9 + kk)*4)*32 + T;
#pragma unroll
            for (int nb = 0; nb < 4; nb++) {
                uint2 bb = bp[nb*32];
                mma_tf32(c[nb], a0, a1, a2, a3, bb.x, bb.y);
            }
        }
    }

    // --- epilogue: bias, store pre-GN, GN stats ---
    int m = T & 3;
    int h_a = h0 + (p0 & 31), w_a = w0 + (p0 >> 5);
    int h_b = h0 + (p1 & 31);
    float* preb = g_pre + (b*CC)*PIX + w_a*256;

    float s[8], qsum[8];
#pragma unroll
    for (int g = 0; g < 8; g++) { s[g] = 0.f; qsum[g] = 0.f; }
#pragma unroll
    for (int nb = 0; nb < 4; nb++) {
        int co0 = nb*8 + 2*m, co1 = co0 + 1;
        float bv0 = __ldg(&bdsc[co0]), bv1 = __ldg(&bdsc[co1]);
        float v00 = c[nb][0] + bv0;
        float v01 = c[nb][1] + bv1;
        float v10 = c[nb][2] + bv0;
        float v11 = c[nb][3] + bv1;
        preb[co0*PIX + h_a] = v00;
        preb[co1*PIX + h_a] = v01;
        preb[co0*PIX + h_b] = v10;
        preb[co1*PIX + h_b] = v11;
        int g = co0 >> 2;
        s[g]    += v00 + v01 + v10 + v11;
        qsum[g] += v00*v00 + v01*v01 + v10*v10 + v11*v11;
    }
#pragma unroll
    for (int g = 0; g < 8; g++) {
        float ss = s[g], qq = qsum[g];
#pragma unroll
        for (int off = 16; off; off >>= 1) {
            ss += __shfl_xor_sync(0xffffffffu, ss, off);
            qq += __shfl_xor_sync(0xffffffffu, qq, off);
        }
        if (T == 0) { atomicAdd(&sOs[g], ss); atomicAdd(&sOq[g], qq); }
    }
    __syncthreads();
    if (tid < 8) {
        atomicAdd(&g_sout[(b*8 + tid)*2 + 0], sOs[tid]);
        atomicAdd(&g_sout[(b*8 + tid)*2 + 1], sOq[tid]);
    }
}

// ------------- K2b: finalize final GN stats (and re-zero accumulators)
__global__ void k_stats_out() {
    int t = threadIdx.x;
    if (t < BB*8) {
        float S = g_sout[t*2], Q = g_sout[t*2 + 1];
        float inv = 1.f / (4.f * (float)PIX);
        float mu  = S * inv;
        float var = Q * inv - mu*mu;
        g_mrout[t*2]     = mu;
        g_mrout[t*2 + 1] = rsqrtf(var + 1e-5f);
        g_sout[t*2]     = 0.f;
        g_sout[t*2 + 1] = 0.f;
    }
}

// ------------------------------------------------------ K5: GN + ReLU -> out
__global__ void k_final(float* __restrict__ out,
                        const float* __restrict__ sc,
                        const float* __restrict__ bi) {
    int i4 = blockIdx.x*256 + threadIdx.x;
    int e  = i4 * 4;
    int c = (e >> 16) & 31;
    int b = e >> 21;
    int g = c >> 2;
    float mu = g_mrout[(b*8 + g)*2], rs = g_mrout[(b*8 + g)*2 + 1];
    float scv = sc[c], biv = bi[c];
    float4 v = *(const float4*)(g_pre + e);
    float4 o;
    o.x = fmaxf(fmaf((v.x - mu)*rs, scv, biv), 0.f);
    o.y = fmaxf(fmaf((v.y - mu)*rs, scv, biv), 0.f);
    o.z = fmaxf(fmaf((v.z - mu)*rs, scv, biv), 0.f);
    o.w = fmaxf(fmaf((v.w - mu)*rs, scv, biv), 0.f);
    *(float4*)(out + e) = o;
}

extern "C" void kernel_launch(void* const* d_in, const int* in_sizes, int n_in,
                              void* d_out, int out_size) {
    const float* x       = (const float*)d_in[0];
    const float* w_off   = (const float*)d_in[1];
    const float* b_off   = (const float*)d_in[2];
    const float* gos     = (const float*)d_in[3];
    const float* gob     = (const float*)d_in[4];
    const float* wdsc    = (const float*)d_in[5];
    const float* bdsc    = (const float*)d_in[6];
    const float* gsc     = (const float*)d_in[7];
    const float* gbi     = (const float*)d_in[8];
    float* out = (float*)d_out;

    cudaFuncSetAttribute(k_main, cudaFuncAttributeMaxDynamicSharedMemorySize, SMEM_MAIN);

    k_conv_off<<<dim3(WW/4, BB), 256>>>(x, w_off, b_off);
    k_stats_off<<<1, 32>>>();
    k_py<<<dim3(PIX/256, BB), 256>>>(gos, gob);
    k_main<<<dim3(HH/32, WW/4, BB), 256, SMEM_MAIN>>>(x, wdsc, bdsc);
    k_stats_out<<<1, 32>>>();
    k_final<<<(BB*CC*PIX)/1024, 256>>>(out, gsc, gbi);
}

// round 10
// speedup vs baseline: 1.3948x; 1.3948x over previous
#include <cuda_runtime.h>
#include <cuda_bf16.h>
#include <math.h>

// Problem constants
#define BB 4
#define CC 32
#define WW 256
#define HH 256
#define KK 9
#define OC_OFF 10
#define PIX (WW*HH)

// k_main (mma) tile: 4 w-rows x 32 h-cols = 128 px, 256 threads (8 warps x 16 px)
#define RR 14              // x rows: w0-5 .. w0+8
#define PCW 43             // pair columns: h0-5 .. h0+37
#define PLANE (RR*PCW)     // 602 float2 per channel
#define NCI2 8
#define XDSZ (NCI2*PLANE)  // 4816 float2

typedef unsigned long long u64;
typedef unsigned int u32;

__device__ __forceinline__ u64 ffma2(u64 a, u64 b, u64 c) {
    u64 d;
    asm("fma.rn.f32x2 %0, %1, %2, %3;" : "=l"(d) : "l"(a), "l"(b), "l"(c));
    return d;
}
__device__ __forceinline__ u64 pack2(float v) {
    u64 d; unsigned u = __float_as_uint(v);
    asm("mov.b64 %0, {%1, %1};" : "=l"(d) : "r"(u));
    return d;
}
__device__ __forceinline__ void unpack2(u64 in, float& lo, float& hi) {
    unsigned a, b;
    asm("mov.b64 {%0, %1}, %2;" : "=r"(a), "=r"(b) : "l"(in));
    lo = __uint_as_float(a); hi = __uint_as_float(b);
}
__device__ __forceinline__ u32 tf32r(float v) {
    u32 r;
    asm("cvt.rna.tf32.f32 %0, %1;" : "=r"(r) : "f"(v));
    return r;
}
__device__ __forceinline__ void mma_tf32(float c[4], u32 a0, u32 a1, u32 a2, u32 a3,
                                         u32 b0, u32 b1) {
    asm("mma.sync.aligned.m16n8k8.row.col.f32.tf32.tf32.f32 "
        "{%0,%1,%2,%3}, {%4,%5,%6,%7}, {%8,%9}, {%0,%1,%2,%3};"
        : "+f"(c[0]), "+f"(c[1]), "+f"(c[2]), "+f"(c[3])
        : "r"(a0), "r"(a1), "r"(a2), "r"(a3), "r"(b0), "r"(b1));
}

// Scratch (zero-initialized at module load; stats arrays are re-zeroed by
// their consumer kernels each run, so every kernel_launch call sees zeros)
__device__ float g_off[BB*OC_OFF*PIX];
__device__ float g_py [BB*KK*PIX];
__device__ float g_pre[BB*CC*PIX];
__device__ uint2 g_bp [4*9*4*32];     // tf32-packed B fragments (mma layout)
__device__ float g_soff[BB*5*2];
__device__ float g_mroff[BB*5*2];
__device__ float g_sout[BB*8*2];
__device__ float g_mrout[BB*8*2];

// ---------------------- K1: 3x3 conv, 32 -> 10 ch, 4 pixels (w-rows) / thread
// (side job: first 18 blocks of batch 0 also pack B fragments into g_bp)
__global__ void __launch_bounds__(256, 2)
k_conv_off(const float* __restrict__ x,
           const float* __restrict__ w_off,
           const float* __restrict__ b_off,
           const float* __restrict__ wdsc) {
    __shared__ __align__(8) float ws[CC*9*OC_OFF];   // [ci][tap][10]
    __shared__ float s_sum[5], s_sq[5];
    int b   = blockIdx.y;
    int wb  = blockIdx.x * 4;
    int tid = threadIdx.x;
    int h   = tid;

    // --- pack B fragments for k_main (independent side job) ---
    if (b == 0 && blockIdx.x < 18) {
        int i = blockIdx.x*256 + tid;
        int lane = i & 31; int rest = i >> 5;
        int nb = rest & 3; rest >>= 2;
        int kk = rest % 9; int q = rest / 9;
        int c8 = lane & 3, co = nb*8 + (lane >> 2);
        float wv0 = wdsc[(co*CC + q*8 + c8)*KK + kk];
        float wv1 = wdsc[(co*CC + q*8 + c8 + 4)*KK + kk];
        g_bp[i] = make_uint2(tf32r(wv0), tf32r(wv1));
    }

    for (int i = tid; i < CC*9*OC_OFF; i += 256) {
        int o = i % OC_OFF; int rest = i / OC_OFF;
        int tap = rest % 9; int ci = rest / 9;
        int dy = tap / 3, dx = tap % 3;
        ws[i] = w_off[((o*CC + ci)*3 + dy)*3 + dx];
    }
    if (tid < 5) { s_sum[tid] = 0.f; s_sq[tid] = 0.f; }
    __syncthreads();

    u64 acc[4][5];
    const u64* b2 = (const u64*)b_off;
#pragma unroll
    for (int p = 0; p < 4; p++)
#pragma unroll
        for (int j = 0; j < 5; j++) acc[p][j] = b2[j];

    const float* xb = x + b*CC*PIX;
#pragma unroll 1
    for (int ci = 0; ci < CC; ci++) {
        const float* xc = xb + ci*PIX;
        u64 v2[6][3];
#pragma unroll
        for (int rr = 0; rr < 6; rr++) {
            int r = wb - 1 + rr;
            bool rok = (unsigned)r < 256u;
#pragma unroll
            for (int dx = 0; dx < 3; dx++) {
                int c = h + dx - 1;
                float v = (rok && (unsigned)c < 256u) ? xc[r*256 + c] : 0.f;
                v2[rr][dx] = pack2(v);
            }
        }
#pragma unroll
        for (int tap = 0; tap < 9; tap++) {
            int dy = tap / 3, dx = tap % 3;
            const u64* wp = (const u64*)&ws[(ci*9 + tap)*OC_OFF];
            u64 w0 = wp[0], w1 = wp[1], w2 = wp[2], w3 = wp[3], w4 = wp[4];
#pragma unroll
            for (int p = 0; p < 4; p++) {
                u64 vv = v2[dy + p][dx];
                acc[p][0] = ffma2(vv, w0, acc[p][0]);
                acc[p][1] = ffma2(vv, w1, acc[p][1]);
                acc[p][2] = ffma2(vv, w2, acc[p][2]);
                acc[p][3] = ffma2(vv, w3, acc[p][3]);
                acc[p][4] = ffma2(vv, w4, acc[p][4]);
            }
        }
    }

    float s[5], q[5];
#pragma unroll
    for (int j = 0; j < 5; j++) { s[j] = 0.f; q[j] = 0.f; }
#pragma unroll
    for (int p = 0; p < 4; p++) {
        int w = wb + p;
        float* outp = g_off + b*OC_OFF*PIX + w*256 + h;
#pragma unroll
        for (int j = 0; j < 5; j++) {
            float v0, v1; unpack2(acc[p][j], v0, v1);
            outp[(2*j)*PIX]   = v0;
            outp[(2*j+1)*PIX] = v1;
            s[j] += v0 + v1;
            q[j] += v0*v0 + v1*v1;
        }
    }
#pragma unroll
    for (int j = 0; j < 5; j++) {
        float ss = s[j], qq = q[j];
#pragma unroll
        for (int off = 16; off; off >>= 1) {
            ss += __shfl_xor_sync(0xffffffffu, ss, off);
            qq += __shfl_xor_sync(0xffffffffu, qq, off);
        }
        if ((tid & 31) == 0) { atomicAdd(&s_sum[j], ss); atomicAdd(&s_sq[j], qq); }
    }
    __syncthreads();
    if (tid < 5) {
        atomicAdd(&g_soff[(b*5 + tid)*2 + 0], s_sum[tid]);
        atomicAdd(&g_soff[(b*5 + tid)*2 + 1], s_sq[tid]);
    }
}

// ------------- K2a: finalize offset GN stats (and re-zero accumulators)
__global__ void k_stats_off() {
    int t = threadIdx.x;
    if (t < BB*5) {
        float S = g_soff[t*2], Q = g_soff[t*2 + 1];
        float inv = 1.f / (2.f * (float)PIX);
        float mu  = S * inv;
        float var = Q * inv - mu*mu;
        g_mroff[t*2]     = mu;
        g_mroff[t*2 + 1] = rsqrtf(var + 1e-5f);
        g_soff[t*2]     = 0.f;
        g_soff[t*2 + 1] = 0.f;
    }
}

// --------------------- K3: GN + tanh + cumsum -> sampling coordinate field py
__global__ void k_py(const float* __restrict__ sc, const float* __restrict__ bi) {
    int b = blockIdx.y;
    int p = blockIdx.x*256 + threadIdx.x;
    int w = p >> 8;

    float t[9];
#pragma unroll
    for (int c = 0; c < 9; c++) {
        float v  = g_off[(b*OC_OFF + c)*PIX + p];
        int   g  = c >> 1;
        float mu = g_mroff[(b*5 + g)*2], rs = g_mroff[(b*5 + g)*2 + 1];
        t[c] = tanhf(fmaf((v - mu)*rs, sc[c], bi[c]));
    }
    float yc[9];
    float r0 = t[3];
    float r1 = r0 + t[2];
    float r2 = r1 + t[1];
    float r3 = r2 + t[0];
    yc[0] = r3; yc[1] = r2; yc[2] = r1; yc[3] = r0;
    yc[4] = 0.f;
    float u0 = t[5];
    float u1 = u0 + t[6];
    float u2 = u1 + t[7];
    float u3 = u2 + t[8];
    yc[5] = u0; yc[6] = u1; yc[7] = u2; yc[8] = u3;

#pragma unroll
    for (int k = 0; k < 9; k++) {
        float y  = (float)w + yc[k];
        float tt = fminf(fmaxf(y * (1.f/256.f), 0.f), 1.f);
        g_py[(b*KK + k)*PIX + p] = tt * 255.f;
    }
}

// -------- K4: fused bilinear-sample + (K,1)-strided conv via tf32 mma.sync
// Smem: geoW @0 (18432) | XsD @18432 (38528) | geoO @56960 (9216) | stat @66176
#define SM_GEOW 0
#define SM_XSD  18432
#define SM_GEOO 56960
#define SM_STAT 66176
#define SMEM_MAIN (66176 + 64)

__global__ void __launch_bounds__(256, 3)
k_main(const float* __restrict__ x,
       const float* __restrict__ bdsc) {
    extern __shared__ __align__(16) char smraw[];
    float4* geoW = (float4*)(smraw + SM_GEOW);
    float2* XsD  = (float2*)(smraw + SM_XSD);
    int2*   geoO = (int2*)  (smraw + SM_GEOO);
    float*  sOs  = (float*) (smraw + SM_STAT);
    float*  sOq  = sOs + 8;

    int b  = blockIdx.z;
    int w0 = blockIdx.y * 4;
    int h0 = blockIdx.x * 32;
    int tid = threadIdx.x;
    int warp = tid >> 5;
    int T = tid & 31;
    int rbase = w0 - 5, cbase = h0 - 5;

    // --- geometry table: per (local px, kk) ---
    for (int i = tid; i < 128*9; i += 256) {
        int kk = i % 9; int p = i / 9;
        int w = w0 + (p >> 5), h = h0 + (p & 31);
        float py = g_py[(b*KK + kk)*PIX + w*256 + h];
        float y0f = floorf(py);
        float wy  = py - y0f;
        int y0 = (int)y0f;
        int y1 = min(y0 + 1, 255);
        int rs0 = y0 - rbase, rs1 = y1 - rbase;
        float fx = (float)(h + kk - 4);
        float pxv = fminf(fmaxf(fx * (1.f/256.f), 0.f), 1.f) * 255.f;
        float x0f = floorf(pxv);
        float wx  = pxv - x0f;
        int cs0 = (int)x0f - cbase;
        geoW[i] = make_float4((1.f-wy)*(1.f-wx), (1.f-wy)*wx, wy*(1.f-wx), wy*wx);
        geoO[i] = make_int2(rs0*PCW + cs0, rs1*PCW + cs0);
    }
    if (tid < 8) { sOs[tid] = 0.f; sOq[tid] = 0.f; }

    float c[4][4];
#pragma unroll
    for (int nb = 0; nb < 4; nb++)
#pragma unroll
        for (int j = 0; j < 4; j++) c[nb][j] = 0.f;

    int p0 = (warp << 4) + (T >> 2);
    int p1 = p0 + 8;
    const float2* Pl0 = XsD + (T & 3)*PLANE;
    const float2* Pl1 = XsD + ((T & 3) + 4)*PLANE;

#pragma unroll 1
    for (int q = 0; q < 4; q++) {
        __syncthreads();
        // stage 8-channel pair tile (divmod indexing, 2 LDG per pair)
        const float* xq = x + (b*CC + q*NCI2)*PIX;
        for (int i = tid; i < XDSZ; i += 256) {
            int cc = i % PCW; int rest = i / PCW;
            int r = rest % RR; int ci8 = rest / RR;
            int gr  = min(max(rbase + r, 0), 255);
            int gc0 = min(max(cbase + cc, 0), 255);
            int gc1 = min(max(cbase + cc + 1, 0), 255);
            const float* xp = xq + ci8*PIX + gr*256;
            XsD[i] = make_float2(xp[gc0], xp[gc1]);
        }
        __syncthreads();

#pragma unroll 1
        for (int kk = 0; kk < 9; kk++) {
            float4 gw0 = geoW[p0*9 + kk]; int2 go0 = geoO[p0*9 + kk];
            float4 gw1 = geoW[p1*9 + kk]; int2 go1 = geoO[p1*9 + kk];

            float2 A00 = Pl0[go0.x], A01 = Pl0[go0.y];
            float v0 = gw0.x*A00.x;
            v0 = fmaf(gw0.y, A00.y, v0);
            v0 = fmaf(gw0.z, A01.x, v0);
            v0 = fmaf(gw0.w, A01.y, v0);
            float2 A10 = Pl0[go1.x], A11 = Pl0[go1.y];
            float v1 = gw1.x*A10.x;
            v1 = fmaf(gw1.y, A10.y, v1);
            v1 = fmaf(gw1.z, A11.x, v1);
            v1 = fmaf(gw1.w, A11.y, v1);
            float2 A20 = Pl1[go0.x], A21 = Pl1[go0.y];
            float v2 = gw0.x*A20.x;
            v2 = fmaf(gw0.y, A20.y, v2);
            v2 = fmaf(gw0.z, A21.x, v2);
            v2 = fmaf(gw0.w, A21.y, v2);
            float2 A30 = Pl1[go1.x], A31 = Pl1[go1.y];
            float v3 = gw1.x*A30.x;
            v3 = fmaf(gw1.y, A30.y, v3);
            v3 = fmaf(gw1.z, A31.x, v3);
            v3 = fmaf(gw1.w, A31.y, v3);

            u32 a0 = tf32r(v0), a1 = tf32r(v1), a2 = tf32r(v2), a3 = tf32r(v3);

            const uint2* bp = g_bp + ((q*9 + kk)*4)*32 + T;
#pragma unroll
            for (int nb = 0; nb < 4; nb++) {
                uint2 bb = __ldg(&bp[nb*32]);
                mma_tf32(c[nb], a0, a1, a2, a3, bb.x, bb.y);
            }
        }
    }

    // --- epilogue: bias, store pre-GN, GN stats ---
    int m = T & 3;
    int h_a = h0 + (p0 & 31), w_a = w0 + (p0 >> 5);
    int h_b = h0 + (p1 & 31);
    float* preb = g_pre + (b*CC)*PIX + w_a*256;

    float s[8], qsum[8];
#pragma unroll
    for (int g = 0; g < 8; g++) { s[g] = 0.f; qsum[g] = 0.f; }
#pragma unroll
    for (int nb = 0; nb < 4; nb++) {
        int co0 = nb*8 + 2*m, co1 = co0 + 1;
        float bv0 = __ldg(&bdsc[co0]), bv1 = __ldg(&bdsc[co1]);
        float v00 = c[nb][0] + bv0;
        float v01 = c[nb][1] + bv1;
        float v10 = c[nb][2] + bv0;
        float v11 = c[nb][3] + bv1;
        preb[co0*PIX + h_a] = v00;
        preb[co1*PIX + h_a] = v01;
        preb[co0*PIX + h_b] = v10;
        preb[co1*PIX + h_b] = v11;
        int g = co0 >> 2;
        s[g]    += v00 + v01 + v10 + v11;
        qsum[g] += v00*v00 + v01*v01 + v10*v10 + v11*v11;
    }
#pragma unroll
    for (int g = 0; g < 8; g++) {
        float ss = s[g], qq = qsum[g];
#pragma unroll
        for (int off = 16; off; off >>= 1) {
            ss += __shfl_xor_sync(0xffffffffu, ss, off);
            qq += __shfl_xor_sync(0xffffffffu, qq, off);
        }
        if (T == 0) { atomicAdd(&sOs[g], ss); atomicAdd(&sOq[g], qq); }
    }
    __syncthreads();
    if (tid < 8) {
        atomicAdd(&g_sout[(b*8 + tid)*2 + 0], sOs[tid]);
        atomicAdd(&g_sout[(b*8 + tid)*2 + 1], sOq[tid]);
    }
}

// ------------- K2b: finalize final GN stats (and re-zero accumulators)
__global__ void k_stats_out() {
    int t = threadIdx.x;
    if (t < BB*8) {
        float S = g_sout[t*2], Q = g_sout[t*2 + 1];
        float inv = 1.f / (4.f * (float)PIX);
        float mu  = S * inv;
        float var = Q * inv - mu*mu;
        g_mrout[t*2]     = mu;
        g_mrout[t*2 + 1] = rsqrtf(var + 1e-5f);
        g_sout[t*2]     = 0.f;
        g_sout[t*2 + 1] = 0.f;
    }
}

// ------------------------------------------------------ K5: GN + ReLU -> out
__global__ void k_final(float* __restrict__ out,
                        const float* __restrict__ sc,
                        const float* __restrict__ bi) {
    int i4 = blockIdx.x*256 + threadIdx.x;
    int e  = i4 * 4;
    int c = (e >> 16) & 31;
    int b = e >> 21;
    int g = c >> 2;
    float mu = g_mrout[(b*8 + g)*2], rs = g_mrout[(b*8 + g)*2 + 1];
    float scv = sc[c], biv = bi[c];
    float4 v = *(const float4*)(g_pre + e);
    float4 o;
    o.x = fmaxf(fmaf((v.x - mu)*rs, scv, biv), 0.f);
    o.y = fmaxf(fmaf((v.y - mu)*rs, scv, biv), 0.f);
    o.z = fmaxf(fmaf((v.z - mu)*rs, scv, biv), 0.f);
    o.w = fmaxf(fmaf((v.w - mu)*rs, scv, biv), 0.f);
    *(float4*)(out + e) = o;
}

extern "C" void kernel_launch(void* const* d_in, const int* in_sizes, int n_in,
                              void* d_out, int out_size) {
    const float* x       = (const float*)d_in[0];
    const float* w_off   = (const float*)d_in[1];
    const float* b_off   = (const float*)d_in[2];
    const float* gos     = (const float*)d_in[3];
    const float* gob     = (const float*)d_in[4];
    const float* wdsc    = (const float*)d_in[5];
    const float* bdsc    = (const float*)d_in[6];
    const float* gsc     = (const float*)d_in[7];
    const float* gbi     = (const float*)d_in[8];
    float* out = (float*)d_out;

    cudaFuncSetAttribute(k_main, cudaFuncAttributeMaxDynamicSharedMemorySize, SMEM_MAIN);

    k_conv_off<<<dim3(WW/4, BB), 256>>>(x, w_off, b_off, wdsc);
    k_stats_off<<<1, 32>>>();
    k_py<<<dim3(PIX/256, BB), 256>>>(gos, gob);
    k_main<<<dim3(HH/32, WW/4, BB), 256, SMEM_MAIN>>>(x, bdsc);
    k_stats_out<<<1, 32>>>();
    k_final<<<(BB*CC*PIX)/1024, 256>>>(out, gsc, gbi);
}

// round 12
// speedup vs baseline: 1.7353x; 1.2442x over previous
#include <cuda_runtime.h>
#include <cuda_bf16.h>
#include <math.h>

// Problem constants
#define BB 4
#define CC 32
#define WW 256
#define HH 256
#define KK 9
#define OC_OFF 10
#define PIX (WW*HH)

// k_main (mma) tile: 4 w-rows x 32 h-cols = 128 px, 256 threads
// warp = 2 w-rows x 8 h-cols (fragment rows r / r+8 share h, adjacent w)
#define RR 14              // x rows: w0-5 .. w0+8
#define PCW 43             // pair columns: h0-5 .. h0+37
#define PPLANE (RR*PCW)    // 602 float4 per channel-pair
#define XQSZ (4*PPLANE)    // 2408 float4 (4 channel-pairs)

typedef unsigned long long u64;
typedef unsigned int u32;

__device__ __forceinline__ u64 ffma2(u64 a, u64 b, u64 c) {
    u64 d;
    asm("fma.rn.f32x2 %0, %1, %2, %3;" : "=l"(d) : "l"(a), "l"(b), "l"(c));
    return d;
}
__device__ __forceinline__ u64 pack2(float v) {
    u64 d; unsigned u = __float_as_uint(v);
    asm("mov.b64 %0, {%1, %1};" : "=l"(d) : "r"(u));
    return d;
}
__device__ __forceinline__ void unpack2(u64 in, float& lo, float& hi) {
    unsigned a, b;
    asm("mov.b64 {%0, %1}, %2;" : "=r"(a), "=r"(b) : "l"(in));
    lo = __uint_as_float(a); hi = __uint_as_float(b);
}
__device__ __forceinline__ u32 tf32r(float v) {
    u32 r;
    asm("cvt.rna.tf32.f32 %0, %1;" : "=r"(r) : "f"(v));
    return r;
}
__device__ __forceinline__ void mma_tf32(float c[4], u32 a0, u32 a1, u32 a2, u32 a3,
                                         u32 b0, u32 b1) {
    asm("mma.sync.aligned.m16n8k8.row.col.f32.tf32.tf32.f32 "
        "{%0,%1,%2,%3}, {%4,%5,%6,%7}, {%8,%9}, {%0,%1,%2,%3};"
        : "+f"(c[0]), "+f"(c[1]), "+f"(c[2]), "+f"(c[3])
        : "r"(a0), "r"(a1), "r"(a2), "r"(a3), "r"(b0), "r"(b1));
}

// Scratch (zero-initialized at module load; stats arrays are re-zeroed by
// their consumer kernels each run)
__device__ float g_off[BB*OC_OFF*PIX];
__device__ float g_py [BB*KK*PIX];
__device__ float g_pre[BB*CC*PIX];
__device__ uint2 g_bp [4*9*4*32];     // tf32-packed B fragments (mma layout)
__device__ float g_soff[BB*5*2];
__device__ float g_mroff[BB*5*2];
__device__ float g_sout[BB*8*2];
__device__ float g_mrout[BB*8*2];

// ---------------------- K1: 3x3 conv, 32 -> 10 ch, 4 pixels (w-rows) / thread
// (side job: first 18 blocks of batch 0 also pack B fragments into g_bp)
__global__ void __launch_bounds__(256, 2)
k_conv_off(const float* __restrict__ x,
           const float* __restrict__ w_off,
           const float* __restrict__ b_off,
           const float* __restrict__ wdsc) {
    __shared__ __align__(8) float ws[CC*9*OC_OFF];   // [ci][tap][10]
    __shared__ float s_sum[5], s_sq[5];
    int b   = blockIdx.y;
    int wb  = blockIdx.x * 4;
    int tid = threadIdx.x;
    int h   = tid;

    // --- pack B fragments for k_main (independent side job) ---
    if (b == 0 && blockIdx.x < 18) {
        int i = blockIdx.x*256 + tid;
        int lane = i & 31; int rest = i >> 5;
        int nb = rest & 3; rest >>= 2;
        int kk = rest % 9; int q = rest / 9;
        int c8 = lane & 3, co = nb*8 + (lane >> 2);
        float wv0 = wdsc[(co*CC + q*8 + c8)*KK + kk];
        float wv1 = wdsc[(co*CC + q*8 + c8 + 4)*KK + kk];
        g_bp[i] = make_uint2(tf32r(wv0), tf32r(wv1));
    }

    for (int i = tid; i < CC*9*OC_OFF; i += 256) {
        int o = i % OC_OFF; int rest = i / OC_OFF;
        int tap = rest % 9; int ci = rest / 9;
        int dy = tap / 3, dx = tap % 3;
        ws[i] = w_off[((o*CC + ci)*3 + dy)*3 + dx];
    }
    if (tid < 5) { s_sum[tid] = 0.f; s_sq[tid] = 0.f; }
    __syncthreads();

    u64 acc[4][5];
    const u64* b2 = (const u64*)b_off;
#pragma unroll
    for (int p = 0; p < 4; p++)
#pragma unroll
        for (int j = 0; j < 5; j++) acc[p][j] = b2[j];

    const float* xb = x + b*CC*PIX;
#pragma unroll 1
    for (int ci = 0; ci < CC; ci++) {
        const float* xc = xb + ci*PIX;
        u64 v2[6][3];
#pragma unroll
        for (int rr = 0; rr < 6; rr++) {
            int r = wb - 1 + rr;
            bool rok = (unsigned)r < 256u;
#pragma unroll
            for (int dx = 0; dx < 3; dx++) {
                int c = h + dx - 1;
                float v = (rok && (unsigned)c < 256u) ? xc[r*256 + c] : 0.f;
                v2[rr][dx] = pack2(v);
            }
        }
#pragma unroll
        for (int tap = 0; tap < 9; tap++) {
            int dy = tap / 3, dx = tap % 3;
            const u64* wp = (const u64*)&ws[(ci*9 + tap)*OC_OFF];
            u64 w0 = wp[0], w1 = wp[1], w2 = wp[2], w3 = wp[3], w4 = wp[4];
#pragma unroll
            for (int p = 0; p < 4; p++) {
                u64 vv = v2[dy + p][dx];
                acc[p][0] = ffma2(vv, w0, acc[p][0]);
                acc[p][1] = ffma2(vv, w1, acc[p][1]);
                acc[p][2] = ffma2(vv, w2, acc[p][2]);
                acc[p][3] = ffma2(vv, w3, acc[p][3]);
                acc[p][4] = ffma2(vv, w4, acc[p][4]);
            }
        }
    }

    float s[5], q[5];
#pragma unroll
    for (int j = 0; j < 5; j++) { s[j] = 0.f; q[j] = 0.f; }
#pragma unroll
    for (int p = 0; p < 4; p++) {
        int w = wb + p;
        float* outp = g_off + b*OC_OFF*PIX + w*256 + h;
#pragma unroll
        for (int j = 0; j < 5; j++) {
            float v0, v1; unpack2(acc[p][j], v0, v1);
            outp[(2*j)*PIX]   = v0;
            outp[(2*j+1)*PIX] = v1;
            s[j] += v0 + v1;
            q[j] += v0*v0 + v1*v1;
        }
    }
#pragma unroll
    for (int j = 0; j < 5; j++) {
        float ss = s[j], qq = q[j];
#pragma unroll
        for (int off = 16; off; off >>= 1) {
            ss += __shfl_xor_sync(0xffffffffu, ss, off);
            qq += __shfl_xor_sync(0xffffffffu, qq, off);
        }
        if ((tid & 31) == 0) { atomicAdd(&s_sum[j], ss); atomicAdd(&s_sq[j], qq); }
    }
    __syncthreads();
    if (tid < 5) {
        atomicAdd(&g_soff[(b*5 + tid)*2 + 0], s_sum[tid]);
        atomicAdd(&g_soff[(b*5 + tid)*2 + 1], s_sq[tid]);
    }
}

// ------------- K2a: finalize offset GN stats (and re-zero accumulators)
__global__ void k_stats_off() {
    int t = threadIdx.x;
    if (t < BB*5) {
        float S = g_soff[t*2], Q = g_soff[t*2 + 1];
        float inv = 1.f / (2.f * (float)PIX);
        float mu  = S * inv;
        float var = Q * inv - mu*mu;
        g_mroff[t*2]     = mu;
        g_mroff[t*2 + 1] = rsqrtf(var + 1e-5f);
        g_soff[t*2]     = 0.f;
        g_soff[t*2 + 1] = 0.f;
    }
}

// --------------------- K3: GN + tanh + cumsum -> sampling coordinate field py
__global__ void k_py(const float* __restrict__ sc, const float* __restrict__ bi) {
    int b = blockIdx.y;
    int p = blockIdx.x*256 + threadIdx.x;
    int w = p >> 8;

    float t[9];
#pragma unroll
    for (int c = 0; c < 9; c++) {
        float v  = g_off[(b*OC_OFF + c)*PIX + p];
        int   g  = c >> 1;
        float mu = g_mroff[(b*5 + g)*2], rs = g_mroff[(b*5 + g)*2 + 1];
        t[c] = tanhf(fmaf((v - mu)*rs, sc[c], bi[c]));
    }
    float yc[9];
    float r0 = t[3];
    float r1 = r0 + t[2];
    float r2 = r1 + t[1];
    float r3 = r2 + t[0];
    yc[0] = r3; yc[1] = r2; yc[2] = r1; yc[3] = r0;
    yc[4] = 0.f;
    float u0 = t[5];
    float u1 = u0 + t[6];
    float u2 = u1 + t[7];
    float u3 = u2 + t[8];
    yc[5] = u0; yc[6] = u1; yc[7] = u2; yc[8] = u3;

#pragma unroll
    for (int k = 0; k < 9; k++) {
        float y  = (float)w + yc[k];
        float tt = fminf(fmaxf(y * (1.f/256.f), 0.f), 1.f);
        g_py[(b*KK + k)*PIX + p] = tt * 255.f;
    }
}

// -------- K4: fused bilinear-sample + (K,1)-strided conv via tf32 mma.sync
// Smem: XsD float4[2408] @0 (38528) | geoP float2[1152] @38528 (9216) | stat @47744
#define SM_XSD  0
#define SM_GEOP 38528
#define SM_STAT 47744
#define SMEM_MAIN (47744 + 64)

__global__ void __launch_bounds__(256, 4)
k_main(const float* __restrict__ x,
       const float* __restrict__ bdsc) {
    extern __shared__ __align__(16) char smraw[];
    float4* XsD  = (float4*)(smraw + SM_XSD);
    float2* geoP = (float2*)(smraw + SM_GEOP);
    float*  sOs  = (float*) (smraw + SM_STAT);
    float*  sOq  = sOs + 8;

    int b  = blockIdx.z;
    int w0 = blockIdx.y * 4;
    int h0 = blockIdx.x * 32;
    int tid = threadIdx.x;
    int warp = tid >> 5;
    int T = tid & 31;
    int rbase = w0 - 5, cbase = h0 - 5;

    // --- packed geometry: per (local px, kk): {wy, rs0*PCW | rs1*PCW<<16} ---
    for (int i = tid; i < 128*9; i += 256) {
        int kk = i % 9; int p = i / 9;
        int w = w0 + (p >> 5), h = h0 + (p & 31);
        float py = g_py[(b*KK + kk)*PIX + w*256 + h];
        float y0f = floorf(py);
        float wy  = py - y0f;
        int y0 = (int)y0f;
        int y1 = min(y0 + 1, 255);
        u32 o01 = (u32)((y0 - rbase)*PCW) | ((u32)((y1 - rbase)*PCW) << 16);
        geoP[i] = make_float2(wy, __uint_as_float(o01));
    }
    if (tid < 8) { sOs[tid] = 0.f; sOq[tid] = 0.f; }

    float c[4][4];
#pragma unroll
    for (int nb = 0; nb < 4; nb++)
#pragma unroll
        for (int j = 0; j < 4; j++) c[nb][j] = 0.f;

    // warp pixel mapping: fragment rows r / r+8 share h, adjacent w
    int r8    = T >> 2;                 // 0..7
    int wbase = (warp >> 2) * 2;        // 0 or 2
    int hcol  = (warp & 3) * 8 + r8;    // 0..31
    int h     = h0 + hcol;
    int pA    = wbase*32 + hcol;        // geo index pixel A (w = w0+wbase)
    int pB    = pA + 32;                // pixel B (w = w0+wbase+1)
    const float4* Pm = XsD + (T & 3)*PPLANE;

#pragma unroll 1
    for (int q = 0; q < 4; q++) {
        __syncthreads();
        // stage 4 channel-pair planes: float4 = {chm(c0),chm(c1),chm4(c0),chm4(c1)}
        const float* xq = x + (b*CC + q*8)*PIX;
        for (int i = tid; i < XQSZ; i += 256) {
            int cc = i % PCW; int rest = i / PCW;
            int r = rest % RR; int mp = rest / RR;
            int gr  = min(max(rbase + r, 0), 255);
            int gc0 = min(max(cbase + cc, 0), 255);
            int gc1 = min(max(cbase + cc + 1, 0), 255);
            const float* pa = xq + mp*PIX + gr*256;
            const float* pb = pa + 4*PIX;
            XsD[i] = make_float4(pa[gc0], pa[gc1], pb[gc0], pb[gc1]);
        }
        __syncthreads();

#pragma unroll 1
        for (int kk = 0; kk < 9; kk++) {
            // column geometry inline — genuinely shared (same h for A and B)
            float fx  = (float)(h + kk - 4);
            float pxv = fminf(fmaxf(fx * (1.f/256.f), 0.f), 1.f) * 255.f;
            float x0f = floorf(pxv);
            float wx  = pxv - x0f;
            int cs0 = (int)x0f - cbase;
            float owx = 1.f - wx;

            // per-px row geometry (packed)
            float2 gA = geoP[pA*9 + kk];
            float wyA = gA.x; u32 oA = __float_as_uint(gA.y);
            int oA0 = (int)(oA & 0xffffu) + cs0, oA1 = (int)(oA >> 16) + cs0;
            float2 gB = geoP[pB*9 + kk];
            float wyB = gB.x; u32 oB = __float_as_uint(gB.y);
            int oB0 = (int)(oB & 0xffffu) + cs0, oB1 = (int)(oB >> 16) + cs0;

            float a00 = (1.f - wyA)*owx, a01 = (1.f - wyA)*wx;
            float a10 = wyA*owx,         a11 = wyA*wx;
            float b00 = (1.f - wyB)*owx, b01 = (1.f - wyB)*wx;
            float b10 = wyB*owx,         b11 = wyB*wx;

            // one LDS.128 per (px,row): both channels, both columns
            float4 f0 = Pm[oA0], f1 = Pm[oA1];
            float4 f2 = Pm[oB0], f3 = Pm[oB1];

            float v0 = a00*f0.x;
            v0 = fmaf(a01, f0.y, v0);
            v0 = fmaf(a10, f1.x, v0);
            v0 = fmaf(a11, f1.y, v0);
            float v2 = a00*f0.z;
            v2 = fmaf(a01, f0.w, v2);
            v2 = fmaf(a10, f1.z, v2);
            v2 = fmaf(a11, f1.w, v2);
            float v1 = b00*f2.x;
            v1 = fmaf(b01, f2.y, v1);
            v1 = fmaf(b10, f3.x, v1);
            v1 = fmaf(b11, f3.y, v1);
            float v3 = b00*f2.z;
            v3 = fmaf(b01, f2.w, v3);
            v3 = fmaf(b10, f3.z, v3);
            v3 = fmaf(b11, f3.w, v3);

            u32 a0 = tf32r(v0), a1 = tf32r(v1), a2 = tf32r(v2), a3 = tf32r(v3);

            const uint2* bp = g_bp + ((q*9 + kk)*4)*32 + T;
#pragma unroll
            for (int nb = 0; nb < 4; nb++) {
                uint2 bb = __ldg(&bp[nb*32]);
                mma_tf32(c[nb], a0, a1, a2, a3, bb.x, bb.y);
            }
        }
    }

    // --- epilogue: bias, store pre-GN, GN stats ---
    int m = T & 3;
    int w_a = w0 + wbase;                       // pixel A row; B is w_a+1
    float* preb = g_pre + (b*CC)*PIX + w_a*256 + h;

    float s[8], qsum[8];
#pragma unroll
    for (int g = 0; g < 8; g++) { s[g] = 0.f; qsum[g] = 0.f; }
#pragma unroll
    for (int nb = 0; nb < 4; nb++) {
        int co0 = nb*8 + 2*m, co1 = co0 + 1;
        float bv0 = __ldg(&bdsc[co0]), bv1 = __ldg(&bdsc[co1]);
        float v00 = c[nb][0] + bv0;
        float v01 = c[nb][1] + bv1;
        float v10 = c[nb][2] + bv0;
        float v11 = c[nb][3] + bv1;
        preb[co0*PIX]       = v00;
        preb[co1*PIX]       = v01;
        preb[co0*PIX + 256] = v10;
        preb[co1*PIX + 256] = v11;
        int g = co0 >> 2;
        s[g]    += v00 + v01 + v10 + v11;
        qsum[g] += v00*v00 + v01*v01 + v10*v10 + v11*v11;
    }
#pragma unroll
    for (int g = 0; g < 8; g++) {
        float ss = s[g], qq = qsum[g];
#pragma unroll
        for (int off = 16; off; off >>= 1) {
            ss += __shfl_xor_sync(0xffffffffu, ss, off);
            qq += __shfl_xor_sync(0xffffffffu, qq, off);
        }
        if (T == 0) { atomicAdd(&sOs[g], ss); atomicAdd(&sOq[g], qq); }
    }
    __syncthreads();
    if (tid < 8) {
        atomicAdd(&g_sout[(b*8 + tid)*2 + 0], sOs[tid]);
        atomicAdd(&g_sout[(b*8 + tid)*2 + 1], sOq[tid]);
    }
}

// ------------- K2b: finalize final GN stats (and re-zero accumulators)
__global__ void k_stats_out() {
    int t = threadIdx.x;
    if (t < BB*8) {
        float S = g_sout[t*2], Q = g_sout[t*2 + 1];
        float inv = 1.f / (4.f * (float)PIX);
        float mu  = S * inv;
        float var = Q * inv - mu*mu;
        g_mrout[t*2]     = mu;
        g_mrout[t*2 + 1] = rsqrtf(var + 1e-5f);
        g_sout[t*2]     = 0.f;
        g_sout[t*2 + 1] = 0.f;
    }
}

// ------------------------------------------------------ K5: GN + ReLU -> out
__global__ void k_final(float* __restrict__ out,
                        const float* __restrict__ sc,
                        const float* __restrict__ bi) {
    int i4 = blockIdx.x*256 + threadIdx.x;
    int e  = i4 * 4;
    int c = (e >> 16) & 31;
    int b = e >> 21;
    int g = c >> 2;
    float mu = g_mrout[(b*8 + g)*2], rs = g_mrout[(b*8 + g)*2 + 1];
    float scv = sc[c], biv = bi[c];
    float4 v = *(const float4*)(g_pre + e);
    float4 o;
    o.x = fmaxf(fmaf((v.x - mu)*rs, scv, biv), 0.f);
    o.y = fmaxf(fmaf((v.y - mu)*rs, scv, biv), 0.f);
    o.z = fmaxf(fmaf((v.z - mu)*rs, scv, biv), 0.f);
    o.w = fmaxf(fmaf((v.w - mu)*rs, scv, biv), 0.f);
    *(float4*)(out + e) = o;
}

extern "C" void kernel_launch(void* const* d_in, const int* in_sizes, int n_in,
                              void* d_out, int out_size) {
    const float* x       = (const float*)d_in[0];
    const float* w_off   = (const float*)d_in[1];
    const float* b_off   = (const float*)d_in[2];
    const float* gos     = (const float*)d_in[3];
    const float* gob     = (const float*)d_in[4];
    const float* wdsc    = (const float*)d_in[5];
    const float* bdsc    = (const float*)d_in[6];
    const float* gsc     = (const float*)d_in[7];
    const float* gbi     = (const float*)d_in[8];
    float* out = (float*)d_out;

    cudaFuncSetAttribute(k_main, cudaFuncAttributeMaxDynamicSharedMemorySize, SMEM_MAIN);

    k_conv_off<<<dim3(WW/4, BB), 256>>>(x, w_off, b_off, wdsc);
    k_stats_off<<<1, 32>>>();
    k_py<<<dim3(PIX/256, BB), 256>>>(gos, gob);
    k_main<<<dim3(HH/32, WW/4, BB), 256, SMEM_MAIN>>>(x, bdsc);
    k_stats_out<<<1, 32>>>();
    k_final<<<(BB*CC*PIX)/1024, 256>>>(out, gsc, gbi);
}